// round 14
// baseline (speedup 1.0000x reference)
#include <cuda_runtime.h>
#include <cuda_fp16.h>
#include <math.h>
#include <stdint.h>

#define NN 50000
#define MM 800000
#define HID 128
#define NHEADS 8
#define CAP 64   // max edges per node bucket (deg ~ Poisson(16); P(>64) ~ 1e-21)

// ---------------- scratch ----------------
__device__ float g_q[NN * HID];
__device__ float g_kv[NN * 2 * HID];
__device__ float g_agg[NN * HID];
__device__ __align__(16) __half g_wbh[128 * 256];
__device__ int g_cnt[NN];
__device__ int g_klist[NN * CAP];
__device__ int g_pos[MM];
__device__ float g_paircsr[(size_t)NN * CAP * 8];

__device__ __forceinline__ unsigned f2tf32(float x) {
    unsigned u; asm("cvt.rna.tf32.f32 %0, %1;" : "=r"(u) : "f"(x)); return u;
}
__device__ __forceinline__ uint32_t smem_u32(const void* p) {
    uint32_t a;
    asm("{ .reg .u64 t; cvta.to.shared.u64 t, %1; cvt.u32.u64 %0, t; }" : "=r"(a) : "l"(p));
    return a;
}

#define LDSM_X4(r0, r1, r2, r3, a) \
    asm volatile("ldmatrix.sync.aligned.m8n8.x4.shared.b16 {%0,%1,%2,%3}, [%4];" \
        : "=r"(r0), "=r"(r1), "=r"(r2), "=r"(r3) : "r"(a))
#define LDSM_X4T(r0, r1, r2, r3, a) \
    asm volatile("ldmatrix.sync.aligned.m8n8.x4.trans.shared.b16 {%0,%1,%2,%3}, [%4];" \
        : "=r"(r0), "=r"(r1), "=r"(r2), "=r"(r3) : "r"(a))
#define MMA16816(d, a0, a1, a2, a3, b0, b1) \
    asm volatile("mma.sync.aligned.m16n8k16.row.col.f32.f16.f16.f32 " \
        "{%0,%1,%2,%3}, {%4,%5,%6,%7}, {%8,%9}, {%0,%1,%2,%3};" \
        : "+f"((d)[0]), "+f"((d)[1]), "+f"((d)[2]), "+f"((d)[3]) \
        : "r"(a0), "r"(a1), "r"(a2), "r"(a3), "r"(b0), "r"(b1))

// ---------------- bucket CSR ----------------
__global__ void init_cnt_kernel() {
    int i = blockIdx.x * 256 + threadIdx.x;
    if (i < NN) g_cnt[i] = 0;
}
__global__ void scatter_kernel(const int* __restrict__ qidx,
                               const int* __restrict__ kidx) {
    int m = blockIdx.x * 256 + threadIdx.x;
    if (m >= MM) return;
    int q = qidx[m];
    int p = atomicAdd(&g_cnt[q], 1);
    if (p >= CAP) p = CAP - 1;      // unreachable statistically; keeps writes in-bounds
    int pos = q * CAP + p;
    g_klist[pos] = kidx[m];
    g_pos[m] = pos;
}

// ---------------- Wb f32 -> f16 ----------------
__global__ void prep_wbh_kernel(const float* __restrict__ Wb) {
    int i = blockIdx.x * 256 + threadIdx.x;
    if (i < 128 * 256) g_wbh[i] = __float2half_rn(Wb[i]);
}

// ---------------- tf32 mma.sync GEMM, K=128 ----------------
__global__ void __launch_bounds__(128) gemm_tf32(
    const float* __restrict__ A, const float* __restrict__ B,
    float* __restrict__ C, int Mrows, int Ncols)
{
    __shared__ unsigned As[64 * 36];
    __shared__ unsigned Bs[32 * 72];
    int t = threadIdx.x, lane = t & 31, wid = t >> 5;
    int wm = wid & 1, wn = wid >> 1;
    int row0 = blockIdx.x * 64, col0 = blockIdx.y * 64;

    float d[2][4][4] = {};

    for (int k0 = 0; k0 < 128; k0 += 32) {
        float4 av[4], bv[4];
#pragma unroll
        for (int i = 0; i < 4; i++) {
            int lin = t + i * 128;
            int ar = lin >> 3, ac = (lin & 7) * 4;
            int arow = row0 + ar; if (arow >= Mrows) arow = Mrows - 1;
            av[i] = *(const float4*)(A + (size_t)arow * 128 + k0 + ac);
            int bk = lin >> 4, bn = (lin & 15) * 4;
            bv[i] = *(const float4*)(B + (size_t)(k0 + bk) * Ncols + col0 + bn);
        }
        __syncthreads();
#pragma unroll
        for (int i = 0; i < 4; i++) {
            int lin = t + i * 128;
            int ar = lin >> 3, ac = (lin & 7) * 4;
            unsigned* p = As + ar * 36 + ac;
            p[0] = f2tf32(av[i].x); p[1] = f2tf32(av[i].y);
            p[2] = f2tf32(av[i].z); p[3] = f2tf32(av[i].w);
            int bk = lin >> 4, bn = (lin & 15) * 4;
            unsigned* q = Bs + bk * 72 + bn;
            q[0] = f2tf32(bv[i].x); q[1] = f2tf32(bv[i].y);
            q[2] = f2tf32(bv[i].z); q[3] = f2tf32(bv[i].w);
        }
        __syncthreads();
#pragma unroll
        for (int kk = 0; kk < 4; kk++) {
            int kb = kk * 8;
            unsigned a[2][4];
#pragma unroll
            for (int mi = 0; mi < 2; mi++) {
                int r = wm * 32 + mi * 16 + (lane >> 2);
                int c = kb + (lane & 3);
                a[mi][0] = As[r * 36 + c];
                a[mi][1] = As[(r + 8) * 36 + c];
                a[mi][2] = As[r * 36 + c + 4];
                a[mi][3] = As[(r + 8) * 36 + c + 4];
            }
#pragma unroll
            for (int nt = 0; nt < 4; nt++) {
                int n = wn * 32 + nt * 8 + (lane >> 2);
                unsigned b0 = Bs[(kb + (lane & 3)) * 72 + n];
                unsigned b1 = Bs[(kb + 4 + (lane & 3)) * 72 + n];
#pragma unroll
                for (int mi = 0; mi < 2; mi++) {
                    asm volatile(
                        "mma.sync.aligned.m16n8k8.row.col.f32.tf32.tf32.f32 "
                        "{%0,%1,%2,%3}, {%4,%5,%6,%7}, {%8,%9}, {%0,%1,%2,%3};"
                        : "+f"(d[mi][nt][0]), "+f"(d[mi][nt][1]),
                          "+f"(d[mi][nt][2]), "+f"(d[mi][nt][3])
                        : "r"(a[mi][0]), "r"(a[mi][1]), "r"(a[mi][2]), "r"(a[mi][3]),
                          "r"(b0), "r"(b1));
                }
            }
        }
    }
#pragma unroll
    for (int mi = 0; mi < 2; mi++)
#pragma unroll
        for (int nt = 0; nt < 4; nt++) {
            int r = row0 + wm * 32 + mi * 16 + (lane >> 2);
            int cc = col0 + wn * 32 + nt * 8 + (lane & 3) * 2;
            if (r < Mrows) {
                C[(size_t)r * Ncols + cc]     = d[mi][nt][0];
                C[(size_t)r * Ncols + cc + 1] = d[mi][nt][1];
            }
            if (r + 8 < Mrows) {
                C[(size_t)(r + 8) * Ncols + cc]     = d[mi][nt][2];
                C[(size_t)(r + 8) * Ncols + cc + 1] = d[mi][nt][3];
            }
        }
}

// ---------------- persistent edge kernel: Wb stationary, X prefetch pipeline ----------------
#define BT_OFF 67584
#define EDGE_SMEM 101376
#define NTILES (MM / 64)

__global__ void __launch_bounds__(256, 2) edge_kernel(
    const float* __restrict__ X,
    const int*   __restrict__ qidx,
    const int*   __restrict__ kidx,
    const float* __restrict__ normptr,
    float*       __restrict__ pair_out)
{
    extern __shared__ unsigned char es[];
    uint32_t sb = smem_u32(es);
    __half* Ws = (__half*)es;                 // [128][264]
    __half* Xs = (__half*)(es + BT_OFF);      // [64][136]
    __half* bt = (__half*)(es + BT_OFF);      // [64][264] (overwrites Xs)

    int t = threadIdx.x, lane = t & 31, wid = t >> 5;
    int wm = wid & 1, wn = wid >> 1;

#pragma unroll
    for (int i = 0; i < 16; i++) {
        int lin = t + i * 256;
        int kr = lin >> 5, n8 = (lin & 31) * 8;
        *(uint4*)(Ws + kr * 264 + n8) = *(const uint4*)(g_wbh + lin * 8);
    }
    float nm = fminf(fmaxf(normptr[0], 1.0f), 16.0f);

    int arow = wm * 32 + (lane & 7) + ((lane >> 3) & 1) * 8;
    int acol = (lane >> 4) * 8;
    int krow_l = (lane & 7) + ((lane >> 3) & 1) * 8;
    int ncol_l = wn * 64 + (lane >> 4) * 8;

    int xr = t >> 5, xc4 = (t & 31) * 4;

    // epilogue mapping: 4 lanes per edge
    int ep_e = wid * 8 + (lane >> 2);     // edge within tile 0..63
    int ep_qc = lane & 3;                 // quarter 0..3

    // prefetch first tile
    float4 xv[8];
    {
        int m0 = blockIdx.x * 64;
#pragma unroll
        for (int i = 0; i < 8; i++)
            xv[i] = *(const float4*)(X + (size_t)(m0 + xr + i * 8) * 128 + xc4);
    }

    for (int tile = blockIdx.x; tile < NTILES; tile += gridDim.x) {
        int m0 = tile * 64;
#pragma unroll
        for (int i = 0; i < 8; i++) {
            __half2* dst = (__half2*)(Xs + (xr + i * 8) * 136 + xc4);
            dst[0] = __floats2half2_rn(xv[i].x, xv[i].y);
            dst[1] = __floats2half2_rn(xv[i].z, xv[i].w);
        }
        __syncthreads();

        float d[2][8][4] = {};
#pragma unroll
        for (int ks = 0; ks < 8; ks++) {
            uint32_t av[8];
            uint32_t a0a = sb + BT_OFF + (uint32_t)((arow * 136 + ks * 16 + acol) * 2);
            LDSM_X4(av[0], av[1], av[2], av[3], a0a);
            LDSM_X4(av[4], av[5], av[6], av[7], a0a + 16 * 136 * 2);
            uint32_t bv[4][4];
            int krow = ks * 16 + krow_l;
#pragma unroll
            for (int bi = 0; bi < 4; bi++) {
                uint32_t ba = sb + (uint32_t)((krow * 264 + ncol_l + bi * 16) * 2);
                LDSM_X4T(bv[bi][0], bv[bi][1], bv[bi][2], bv[bi][3], ba);
            }
#pragma unroll
            for (int nt = 0; nt < 8; nt++) {
                uint32_t b0 = bv[nt >> 1][(nt & 1) * 2];
                uint32_t b1 = bv[nt >> 1][(nt & 1) * 2 + 1];
                MMA16816(d[0][nt], av[0], av[1], av[2], av[3], b0, b1);
                MMA16816(d[1][nt], av[4], av[5], av[6], av[7], b0, b1);
            }
        }

        __syncthreads();   // Xs dead; write btile f16
#pragma unroll
        for (int mi = 0; mi < 2; mi++)
#pragma unroll
            for (int nt = 0; nt < 8; nt++) {
                int r = wm * 32 + mi * 16 + (lane >> 2);
                int cc = wn * 64 + nt * 8 + (lane & 3) * 2;
                *(__half2*)(bt + r * 264 + cc) =
                    __floats2half2_rn(d[mi][nt][0], d[mi][nt][1]);
                *(__half2*)(bt + (r + 8) * 264 + cc) =
                    __floats2half2_rn(d[mi][nt][2], d[mi][nt][3]);
            }

        // prefetch NEXT tile's X — overlaps epilogue
        int tn = tile + gridDim.x;
        if (tn < NTILES) {
            int mn = tn * 64;
#pragma unroll
            for (int i = 0; i < 8; i++)
                xv[i] = *(const float4*)(X + (size_t)(mn + xr + i * 8) * 128 + xc4);
        }
        __syncthreads();

        // ---- epilogue v2: 4 lanes per edge, float4 gathers ----
        {
            int m = m0 + ep_e;
            int qi = qidx[m], ki = kidx[m];
            const float* qrow = g_q  + (size_t)qi * 128 + ep_qc * 32;
            const float* krow = g_kv + (size_t)ki * 256 + ep_qc * 32;
            const __half* btm = bt + ep_e * 264 + ep_qc * 32;
            float accE[4] = {}, accO[4] = {};
#pragma unroll
            for (int j = 0; j < 8; j++) {
                float4 q4 = *(const float4*)(qrow + j * 4);
                float4 k4 = *(const float4*)(krow + j * 4);
                __half2 bmp[2], bap[2];
                *(uint2*)bmp = *(const uint2*)(btm + j * 4);
                *(uint2*)bap = *(const uint2*)(btm + 128 + j * 4);
                float2 bm0 = __half22float2(bmp[0]), bm1 = __half22float2(bmp[1]);
                float2 ba0 = __half22float2(bap[0]), ba1 = __half22float2(bap[1]);
                float* acc = (j & 1) ? accO : accE;
                acc[0] += q4.x * (fmaf(k4.x, bm0.x, k4.x) + ba0.x);
                acc[1] += q4.y * (fmaf(k4.y, bm0.y, k4.y) + ba0.y);
                acc[2] += q4.z * (fmaf(k4.z, bm1.x, k4.z) + ba1.x);
                acc[3] += q4.w * (fmaf(k4.w, bm1.y, k4.w) + ba1.y);
            }
            // reduce over the 4 lanes of this edge (lanes are consecutive, xor 1,2)
#pragma unroll
            for (int off = 1; off < 4; off <<= 1) {
#pragma unroll
                for (int i = 0; i < 4; i++) {
                    accE[i] += __shfl_xor_sync(0xffffffffu, accE[i], off);
                    accO[i] += __shfl_xor_sync(0xffffffffu, accO[i], off);
                }
            }
            float inm = 1.0f / nm;
            int pos = g_pos[m];
            if (ep_qc == 0) {
                float4 lg = make_float4(accE[0] * inm, accE[1] * inm,
                                        accE[2] * inm, accE[3] * inm);
                *(float4*)(pair_out + (size_t)m * 8) = lg;
                *(float4*)(g_paircsr + (size_t)pos * 8) = lg;
            } else if (ep_qc == 1) {
                float4 lg = make_float4(accO[0] * inm, accO[1] * inm,
                                        accO[2] * inm, accO[3] * inm);
                *(float4*)(pair_out + (size_t)m * 8 + 4) = lg;
                *(float4*)(g_paircsr + (size_t)pos * 8 + 4) = lg;
            }
        }
        __syncthreads();
    }
}

// ---------------- per-node softmax + aggregation (bucket CSR, attn cached) ----------------
__global__ void __launch_bounds__(256) node_agg_kernel()
{
    __shared__ float sattn[8][CAP * 8];   // per-warp attn cache (16 KB)
    int w = threadIdx.x >> 5;
    int node = (blockIdx.x * 256 + threadIdx.x) >> 5;
    int lane = threadIdx.x & 31;
    if (node >= NN) return;
    int cnt = g_cnt[node];
    if (cnt > CAP) cnt = CAP;

    float* orow = g_agg + (size_t)node * 128;
    if (cnt == 0) {
        *(float4*)(orow + lane * 4) = make_float4(0.f, 0.f, 0.f, 0.f);
        return;
    }
    const float* prow = g_paircsr + (size_t)node * CAP * 8;
    const int* kl = g_klist + node * CAP;

    int kl0 = (lane < cnt) ? kl[lane] : 0;
    int kl1 = (32 + lane < cnt) ? kl[32 + lane] : 0;

    // phase 1: online (m, s) per head; lane -> head lane&7, edges strided by 4
    int h = lane & 7;
    float mx = __int_as_float(0xff800000);
    float sm = 0.0f;
    for (int i = lane >> 3; i < cnt; i += 4) {
        float val = prow[(size_t)i * 8 + h];
        float nmx = fmaxf(mx, val);
        sm = sm * __expf(mx - nmx) + __expf(val - nmx);
        mx = nmx;
    }
#pragma unroll
    for (int off = 8; off < 32; off <<= 1) {
        float mo = __shfl_xor_sync(0xffffffffu, mx, off);
        float so = __shfl_xor_sync(0xffffffffu, sm, off);
        float nmx = fmaxf(mx, mo);
        float ea = (mx == nmx) ? 1.0f : __expf(mx - nmx);
        float eb = (mo == nmx) ? 1.0f : __expf(mo - nmx);
        sm = sm * ea + so * eb;
        mx = nmx;
    }
    // every lane now holds final (mx, sm) for head lane&7
    float ish = 1.0f / sm;

    // phase 1.5: attn per (edge, head) once -> smem
    for (int idx = lane; idx < cnt * 8; idx += 32)   // idx&7 == lane&7 invariant
        sattn[w][idx] = __expf(prow[idx] - mx) * ish;
    __syncwarp();

    // phase 2: accumulate attn * v — no exp, float4 everywhere
    float a0 = 0.f, a1 = 0.f, a2 = 0.f, a3 = 0.f;
    int hb4 = (lane & 1) * 4;   // head base for this lane's channels (lane*4)&7
#pragma unroll 4
    for (int i = 0; i < cnt; i++) {
        int ki = __shfl_sync(0xffffffffu, (i < 32) ? kl0 : kl1, i & 31);
        float4 at = *(const float4*)(&sattn[w][i * 8 + hb4]);
        float4 v = *(const float4*)(g_kv + (size_t)ki * 256 + 128 + lane * 4);
        a0 += at.x * v.x;
        a1 += at.y * v.y;
        a2 += at.z * v.z;
        a3 += at.w * v.w;
    }
    *(float4*)(orow + lane * 4) = make_float4(a0, a1, a2, a3);
}

// ---------------- host ----------------
static float* symaddr(const void* sym) {
    void* p = nullptr;
    cudaGetSymbolAddress(&p, sym);
    return (float*)p;
}

extern "C" void kernel_launch(void* const* d_in, const int* in_sizes, int n_in,
                              void* d_out, int out_size)
{
    const float* query  = (const float*)d_in[0];
    const float* key    = (const float*)d_in[1];
    const float* inter  = (const float*)d_in[2];
    const int*   qidx   = (const int*)d_in[3];
    const int*   kidx   = (const int*)d_in[4];
    const float* Wq     = (const float*)d_in[5];
    const float* Wkv    = (const float*)d_in[6];
    const float* Wb     = (const float*)d_in[7];
    const float* Wo     = (const float*)d_in[8];
    const float* normp  = (const float*)d_in[9];

    float* out_result = (float*)d_out;
    float* out_pair   = (float*)d_out + (size_t)NN * HID;

    float* dq   = symaddr(g_q);
    float* dkv  = symaddr(g_kv);
    float* dagg = symaddr(g_agg);

    static bool init_done = false;
    static cudaStream_t s2;
    static cudaEvent_t ev_fork, ev_join;
    if (!init_done) {
        cudaFuncSetAttribute(edge_kernel,
                             cudaFuncAttributeMaxDynamicSharedMemorySize, EDGE_SMEM);
        cudaStreamCreateWithFlags(&s2, cudaStreamNonBlocking);
        cudaEventCreateWithFlags(&ev_fork, cudaEventDisableTiming);
        cudaEventCreateWithFlags(&ev_join, cudaEventDisableTiming);
        init_done = true;
    }

    // fork: bucket CSR on side stream
    cudaEventRecord(ev_fork, 0);
    cudaStreamWaitEvent(s2, ev_fork, 0);
    init_cnt_kernel<<<(NN + 255) / 256, 256, 0, s2>>>();
    scatter_kernel<<<MM / 256, 256, 0, s2>>>(qidx, kidx);
    cudaEventRecord(ev_join, s2);

    // main stream: projections
    prep_wbh_kernel<<<128, 256>>>(Wb);
    gemm_tf32<<<dim3((NN + 63) / 64, 2), 128>>>(query, Wq, dq, NN, 128);
    gemm_tf32<<<dim3((NN + 63) / 64, 4), 128>>>(key, Wkv, dkv, NN, 256);

    // join: edge kernel needs projections + g_pos
    cudaStreamWaitEvent(0, ev_join, 0);
    edge_kernel<<<296, 256, EDGE_SMEM>>>(inter, qidx, kidx, normp, out_pair);

    node_agg_kernel<<<(NN * 32 + 255) / 256, 256>>>();
    gemm_tf32<<<dim3((NN + 63) / 64, 2), 128>>>(dagg, Wo, out_result, NN, 128);
}

// round 15
// speedup vs baseline: 1.4189x; 1.4189x over previous
#include <cuda_runtime.h>
#include <cuda_fp16.h>
#include <math.h>
#include <stdint.h>

#define NN 50000
#define MM 800000
#define HID 128
#define NHEADS 8
#define CAP 64   // max edges per node bucket (deg ~ Poisson(16); P(>64) ~ 1e-21)

// ---------------- scratch ----------------
__device__ float g_q[NN * HID];
__device__ float g_kv[NN * 2 * HID];
__device__ float g_agg[NN * HID];
__device__ __align__(16) __half g_wbh[128 * 256];
__device__ int g_cnt[NN];
__device__ int g_klist[NN * CAP];
__device__ int g_pos[MM];
__device__ float g_paircsr[(size_t)NN * CAP * 8];

__device__ __forceinline__ unsigned f2tf32(float x) {
    unsigned u; asm("cvt.rna.tf32.f32 %0, %1;" : "=r"(u) : "f"(x)); return u;
}
__device__ __forceinline__ uint32_t smem_u32(const void* p) {
    uint32_t a;
    asm("{ .reg .u64 t; cvta.to.shared.u64 t, %1; cvt.u32.u64 %0, t; }" : "=r"(a) : "l"(p));
    return a;
}

#define LDSM_X4(r0, r1, r2, r3, a) \
    asm volatile("ldmatrix.sync.aligned.m8n8.x4.shared.b16 {%0,%1,%2,%3}, [%4];" \
        : "=r"(r0), "=r"(r1), "=r"(r2), "=r"(r3) : "r"(a))
#define LDSM_X4T(r0, r1, r2, r3, a) \
    asm volatile("ldmatrix.sync.aligned.m8n8.x4.trans.shared.b16 {%0,%1,%2,%3}, [%4];" \
        : "=r"(r0), "=r"(r1), "=r"(r2), "=r"(r3) : "r"(a))
#define MMA16816(d, a0, a1, a2, a3, b0, b1) \
    asm volatile("mma.sync.aligned.m16n8k16.row.col.f32.f16.f16.f32 " \
        "{%0,%1,%2,%3}, {%4,%5,%6,%7}, {%8,%9}, {%0,%1,%2,%3};" \
        : "+f"((d)[0]), "+f"((d)[1]), "+f"((d)[2]), "+f"((d)[3]) \
        : "r"(a0), "r"(a1), "r"(a2), "r"(a3), "r"(b0), "r"(b1))

// ---------------- bucket CSR ----------------
__global__ void init_cnt_kernel() {
    int i = blockIdx.x * 256 + threadIdx.x;
    if (i < NN) g_cnt[i] = 0;
}
__global__ void scatter_kernel(const int* __restrict__ qidx,
                               const int* __restrict__ kidx) {
    int m = blockIdx.x * 256 + threadIdx.x;
    if (m >= MM) return;
    int q = qidx[m];
    int p = atomicAdd(&g_cnt[q], 1);
    if (p >= CAP) p = CAP - 1;      // unreachable statistically; keeps writes in-bounds
    int pos = q * CAP + p;
    g_klist[pos] = kidx[m];
    g_pos[m] = pos;
}

// ---------------- Wb f32 -> f16 ----------------
__global__ void prep_wbh_kernel(const float* __restrict__ Wb) {
    int i = blockIdx.x * 256 + threadIdx.x;
    if (i < 128 * 256) g_wbh[i] = __float2half_rn(Wb[i]);
}

// ---------------- tf32 mma.sync GEMM, K=128 ----------------
__global__ void __launch_bounds__(128) gemm_tf32(
    const float* __restrict__ A, const float* __restrict__ B,
    float* __restrict__ C, int Mrows, int Ncols)
{
    __shared__ unsigned As[64 * 36];
    __shared__ unsigned Bs[32 * 72];
    int t = threadIdx.x, lane = t & 31, wid = t >> 5;
    int wm = wid & 1, wn = wid >> 1;
    int row0 = blockIdx.x * 64, col0 = blockIdx.y * 64;

    float d[2][4][4] = {};

    for (int k0 = 0; k0 < 128; k0 += 32) {
        float4 av[4], bv[4];
#pragma unroll
        for (int i = 0; i < 4; i++) {
            int lin = t + i * 128;
            int ar = lin >> 3, ac = (lin & 7) * 4;
            int arow = row0 + ar; if (arow >= Mrows) arow = Mrows - 1;
            av[i] = *(const float4*)(A + (size_t)arow * 128 + k0 + ac);
            int bk = lin >> 4, bn = (lin & 15) * 4;
            bv[i] = *(const float4*)(B + (size_t)(k0 + bk) * Ncols + col0 + bn);
        }
        __syncthreads();
#pragma unroll
        for (int i = 0; i < 4; i++) {
            int lin = t + i * 128;
            int ar = lin >> 3, ac = (lin & 7) * 4;
            unsigned* p = As + ar * 36 + ac;
            p[0] = f2tf32(av[i].x); p[1] = f2tf32(av[i].y);
            p[2] = f2tf32(av[i].z); p[3] = f2tf32(av[i].w);
            int bk = lin >> 4, bn = (lin & 15) * 4;
            unsigned* q = Bs + bk * 72 + bn;
            q[0] = f2tf32(bv[i].x); q[1] = f2tf32(bv[i].y);
            q[2] = f2tf32(bv[i].z); q[3] = f2tf32(bv[i].w);
        }
        __syncthreads();
#pragma unroll
        for (int kk = 0; kk < 4; kk++) {
            int kb = kk * 8;
            unsigned a[2][4];
#pragma unroll
            for (int mi = 0; mi < 2; mi++) {
                int r = wm * 32 + mi * 16 + (lane >> 2);
                int c = kb + (lane & 3);
                a[mi][0] = As[r * 36 + c];
                a[mi][1] = As[(r + 8) * 36 + c];
                a[mi][2] = As[r * 36 + c + 4];
                a[mi][3] = As[(r + 8) * 36 + c + 4];
            }
#pragma unroll
            for (int nt = 0; nt < 4; nt++) {
                int n = wn * 32 + nt * 8 + (lane >> 2);
                unsigned b0 = Bs[(kb + (lane & 3)) * 72 + n];
                unsigned b1 = Bs[(kb + 4 + (lane & 3)) * 72 + n];
#pragma unroll
                for (int mi = 0; mi < 2; mi++) {
                    asm volatile(
                        "mma.sync.aligned.m16n8k8.row.col.f32.tf32.tf32.f32 "
                        "{%0,%1,%2,%3}, {%4,%5,%6,%7}, {%8,%9}, {%0,%1,%2,%3};"
                        : "+f"(d[mi][nt][0]), "+f"(d[mi][nt][1]),
                          "+f"(d[mi][nt][2]), "+f"(d[mi][nt][3])
                        : "r"(a[mi][0]), "r"(a[mi][1]), "r"(a[mi][2]), "r"(a[mi][3]),
                          "r"(b0), "r"(b1));
                }
            }
        }
    }
#pragma unroll
    for (int mi = 0; mi < 2; mi++)
#pragma unroll
        for (int nt = 0; nt < 4; nt++) {
            int r = row0 + wm * 32 + mi * 16 + (lane >> 2);
            int cc = col0 + wn * 32 + nt * 8 + (lane & 3) * 2;
            if (r < Mrows) {
                C[(size_t)r * Ncols + cc]     = d[mi][nt][0];
                C[(size_t)r * Ncols + cc + 1] = d[mi][nt][1];
            }
            if (r + 8 < Mrows) {
                C[(size_t)(r + 8) * Ncols + cc]     = d[mi][nt][2];
                C[(size_t)(r + 8) * Ncols + cc + 1] = d[mi][nt][3];
            }
        }
}

// ---------------- persistent edge kernel: Wb stationary, X prefetch pipeline ----------------
// (EXACT Round-13 version — scalar epilogue, low register pressure)
#define BT_OFF 67584
#define EDGE_SMEM 101376
#define NTILES (MM / 64)

__global__ void __launch_bounds__(256, 2) edge_kernel(
    const float* __restrict__ X,
    const int*   __restrict__ qidx,
    const int*   __restrict__ kidx,
    const float* __restrict__ normptr,
    float*       __restrict__ pair_out)
{
    extern __shared__ unsigned char es[];
    uint32_t sb = smem_u32(es);
    __half* Ws = (__half*)es;                 // [128][264]
    __half* Xs = (__half*)(es + BT_OFF);      // [64][136]
    __half* bt = (__half*)(es + BT_OFF);      // [64][264] (overwrites Xs)

    int t = threadIdx.x, lane = t & 31, wid = t >> 5;
    int wm = wid & 1, wn = wid >> 1;

#pragma unroll
    for (int i = 0; i < 16; i++) {
        int lin = t + i * 256;
        int kr = lin >> 5, n8 = (lin & 31) * 8;
        *(uint4*)(Ws + kr * 264 + n8) = *(const uint4*)(g_wbh + lin * 8);
    }
    float nm = fminf(fmaxf(normptr[0], 1.0f), 16.0f);

    int arow = wm * 32 + (lane & 7) + ((lane >> 3) & 1) * 8;
    int acol = (lane >> 4) * 8;
    int krow_l = (lane & 7) + ((lane >> 3) & 1) * 8;
    int ncol_l = wn * 64 + (lane >> 4) * 8;

    int xr = t >> 5, xc4 = (t & 31) * 4;

    // prefetch first tile
    float4 xv[8];
    {
        int m0 = blockIdx.x * 64;
#pragma unroll
        for (int i = 0; i < 8; i++)
            xv[i] = *(const float4*)(X + (size_t)(m0 + xr + i * 8) * 128 + xc4);
    }

    for (int tile = blockIdx.x; tile < NTILES; tile += gridDim.x) {
        int m0 = tile * 64;
#pragma unroll
        for (int i = 0; i < 8; i++) {
            __half2* dst = (__half2*)(Xs + (xr + i * 8) * 136 + xc4);
            dst[0] = __floats2half2_rn(xv[i].x, xv[i].y);
            dst[1] = __floats2half2_rn(xv[i].z, xv[i].w);
        }
        __syncthreads();

        float d[2][8][4] = {};
#pragma unroll
        for (int ks = 0; ks < 8; ks++) {
            uint32_t av[8];
            uint32_t a0a = sb + BT_OFF + (uint32_t)((arow * 136 + ks * 16 + acol) * 2);
            LDSM_X4(av[0], av[1], av[2], av[3], a0a);
            LDSM_X4(av[4], av[5], av[6], av[7], a0a + 16 * 136 * 2);
            uint32_t bv[4][4];
            int krow = ks * 16 + krow_l;
#pragma unroll
            for (int bi = 0; bi < 4; bi++) {
                uint32_t ba = sb + (uint32_t)((krow * 264 + ncol_l + bi * 16) * 2);
                LDSM_X4T(bv[bi][0], bv[bi][1], bv[bi][2], bv[bi][3], ba);
            }
#pragma unroll
            for (int nt = 0; nt < 8; nt++) {
                uint32_t b0 = bv[nt >> 1][(nt & 1) * 2];
                uint32_t b1 = bv[nt >> 1][(nt & 1) * 2 + 1];
                MMA16816(d[0][nt], av[0], av[1], av[2], av[3], b0, b1);
                MMA16816(d[1][nt], av[4], av[5], av[6], av[7], b0, b1);
            }
        }

        __syncthreads();   // Xs dead; write btile f16
#pragma unroll
        for (int mi = 0; mi < 2; mi++)
#pragma unroll
            for (int nt = 0; nt < 8; nt++) {
                int r = wm * 32 + mi * 16 + (lane >> 2);
                int cc = wn * 64 + nt * 8 + (lane & 3) * 2;
                *(__half2*)(bt + r * 264 + cc) =
                    __floats2half2_rn(d[mi][nt][0], d[mi][nt][1]);
                *(__half2*)(bt + (r + 8) * 264 + cc) =
                    __floats2half2_rn(d[mi][nt][2], d[mi][nt][3]);
            }

        // prefetch NEXT tile's X now — overlaps the epilogue below
        int tn = tile + gridDim.x;
        if (tn < NTILES) {
            int mn = tn * 64;
#pragma unroll
            for (int i = 0; i < 8; i++)
                xv[i] = *(const float4*)(X + (size_t)(mn + xr + i * 8) * 128 + xc4);
        }
        __syncthreads();

        // epilogue: 512 (edge, head) items, 2 per thread
#pragma unroll
        for (int it = 0; it < 2; it++) {
            int item = t + it * 256;
            int e = item >> 3, h = item & 7;
            int m = m0 + e;
            int qi = qidx[m], ki = kidx[m];
            const float* qrow = g_q  + (size_t)qi * 128;
            const float* krow = g_kv + (size_t)ki * 256;
            float accl = 0.0f;
#pragma unroll
            for (int dd = 0; dd < 16; dd++) {
                int c = dd * 8 + h;
                float kvv = krow[c];
                float bm = __half2float(bt[e * 264 + c]);
                float ba = __half2float(bt[e * 264 + 128 + c]);
                accl += qrow[c] * (fmaf(kvv, bm, kvv) + ba);
            }
            float lg = accl / nm;
            pair_out[(size_t)m * 8 + h] = lg;
            g_paircsr[(size_t)g_pos[m] * 8 + h] = lg;
        }
        __syncthreads();
    }
}

// ---------------- per-node softmax + aggregation (bucket CSR, attn cached) ----------------
__global__ void __launch_bounds__(256) node_agg_kernel()
{
    __shared__ float sattn[8][CAP * 8];   // per-warp attn cache (16 KB)
    int w = threadIdx.x >> 5;
    int node = (blockIdx.x * 256 + threadIdx.x) >> 5;
    int lane = threadIdx.x & 31;
    if (node >= NN) return;
    int cnt = g_cnt[node];
    if (cnt > CAP) cnt = CAP;

    float* orow = g_agg + (size_t)node * 128;
    if (cnt == 0) {
        *(float4*)(orow + lane * 4) = make_float4(0.f, 0.f, 0.f, 0.f);
        return;
    }
    const float* prow = g_paircsr + (size_t)node * CAP * 8;
    const int* kl = g_klist + node * CAP;

    int kl0 = (lane < cnt) ? kl[lane] : 0;
    int kl1 = (32 + lane < cnt) ? kl[32 + lane] : 0;

    // phase 1: online (m, s) per head; lane -> head lane&7, edges strided by 4
    int h = lane & 7;
    float mx = __int_as_float(0xff800000);
    float sm = 0.0f;
    for (int i = lane >> 3; i < cnt; i += 4) {
        float val = prow[(size_t)i * 8 + h];
        float nmx = fmaxf(mx, val);
        sm = sm * __expf(mx - nmx) + __expf(val - nmx);
        mx = nmx;
    }
#pragma unroll
    for (int off = 8; off < 32; off <<= 1) {
        float mo = __shfl_xor_sync(0xffffffffu, mx, off);
        float so = __shfl_xor_sync(0xffffffffu, sm, off);
        float nmx = fmaxf(mx, mo);
        float ea = (mx == nmx) ? 1.0f : __expf(mx - nmx);
        float eb = (mo == nmx) ? 1.0f : __expf(mo - nmx);
        sm = sm * ea + so * eb;
        mx = nmx;
    }
    // every lane now holds final (mx, sm) for head lane&7
    float ish = 1.0f / sm;

    // phase 1.5: attn per (edge, head) once -> smem (idx&7 == lane&7 invariant)
    for (int idx = lane; idx < cnt * 8; idx += 32)
        sattn[w][idx] = __expf(prow[idx] - mx) * ish;
    __syncwarp();

    // phase 2: accumulate attn * v — no exp, float4 everywhere
    float a0 = 0.f, a1 = 0.f, a2 = 0.f, a3 = 0.f;
    int hb4 = (lane & 1) * 4;   // head base for this lane's channels (lane*4)&7
#pragma unroll 4
    for (int i = 0; i < cnt; i++) {
        int ki = __shfl_sync(0xffffffffu, (i < 32) ? kl0 : kl1, i & 31);
        float4 at = *(const float4*)(&sattn[w][i * 8 + hb4]);
        float4 v = *(const float4*)(g_kv + (size_t)ki * 256 + 128 + lane * 4);
        a0 += at.x * v.x;
        a1 += at.y * v.y;
        a2 += at.z * v.z;
        a3 += at.w * v.w;
    }
    *(float4*)(orow + lane * 4) = make_float4(a0, a1, a2, a3);
}

// ---------------- host ----------------
static float* symaddr(const void* sym) {
    void* p = nullptr;
    cudaGetSymbolAddress(&p, sym);
    return (float*)p;
}

extern "C" void kernel_launch(void* const* d_in, const int* in_sizes, int n_in,
                              void* d_out, int out_size)
{
    const float* query  = (const float*)d_in[0];
    const float* key    = (const float*)d_in[1];
    const float* inter  = (const float*)d_in[2];
    const int*   qidx   = (const int*)d_in[3];
    const int*   kidx   = (const int*)d_in[4];
    const float* Wq     = (const float*)d_in[5];
    const float* Wkv    = (const float*)d_in[6];
    const float* Wb     = (const float*)d_in[7];
    const float* Wo     = (const float*)d_in[8];
    const float* normp  = (const float*)d_in[9];

    float* out_result = (float*)d_out;
    float* out_pair   = (float*)d_out + (size_t)NN * HID;

    float* dq   = symaddr(g_q);
    float* dkv  = symaddr(g_kv);
    float* dagg = symaddr(g_agg);

    static bool init_done = false;
    static cudaStream_t s2;
    static cudaEvent_t ev_fork, ev_join;
    if (!init_done) {
        cudaFuncSetAttribute(edge_kernel,
                             cudaFuncAttributeMaxDynamicSharedMemorySize, EDGE_SMEM);
        cudaStreamCreateWithFlags(&s2, cudaStreamNonBlocking);
        cudaEventCreateWithFlags(&ev_fork, cudaEventDisableTiming);
        cudaEventCreateWithFlags(&ev_join, cudaEventDisableTiming);
        init_done = true;
    }

    // fork: bucket CSR on side stream
    cudaEventRecord(ev_fork, 0);
    cudaStreamWaitEvent(s2, ev_fork, 0);
    init_cnt_kernel<<<(NN + 255) / 256, 256, 0, s2>>>();
    scatter_kernel<<<MM / 256, 256, 0, s2>>>(qidx, kidx);
    cudaEventRecord(ev_join, s2);

    // main stream: projections
    prep_wbh_kernel<<<128, 256>>>(Wb);
    gemm_tf32<<<dim3((NN + 63) / 64, 2), 128>>>(query, Wq, dq, NN, 128);
    gemm_tf32<<<dim3((NN + 63) / 64, 4), 128>>>(key, Wkv, dkv, NN, 256);

    // join: edge kernel needs projections + g_pos
    cudaStreamWaitEvent(0, ev_join, 0);
    edge_kernel<<<296, 256, EDGE_SMEM>>>(inter, qidx, kidx, normp, out_pair);

    node_agg_kernel<<<(NN * 32 + 255) / 256, 256>>>();
    gemm_tf32<<<dim3((NN + 63) / 64, 2), 128>>>(dagg, Wo, out_result, NN, 128);
}